// round 3
// baseline (speedup 1.0000x reference)
#include <cuda_runtime.h>
#include <math.h>
#include <limits.h>
#include <stdint.h>

#define BB 8
#define KK 512
#define DD 16
#define MAX_CPN 512
#define CPBUF 1024
#define BG_W 2.0f

#define NB 148      // persistent blocks (<= 152 SMs on GB300, all co-resident)
#define NT 512

// ---------------- device scratch ----------------
__device__ float4 g_acc[BB*KK];        // {cnt, sumexp, dsum, pad}
__device__ int    g_cpcnt[BB*KK];
__device__ int    g_fi[BB*KK];
__device__ float  g_cpbeta[BB*KK];
__device__ float  g_ref[BB*KK*DD];
__device__ int    g_ncp[BB];
__device__ int    g_nbg[BB];
__device__ float  g_bgsig[BB];
__device__ int    g_cpidx[BB*CPBUF];
__device__ float  g_rep[BB];
__device__ volatile unsigned g_bar[8];

// ---------------- launch 1: zero everything (incl. barrier counters) ----------------
__global__ void zero_kernel() {
    int idx = blockIdx.x * blockDim.x + threadIdx.x;
    int stride = gridDim.x * blockDim.x;
    for (int i = idx; i < BB*KK; i += stride) {
        g_acc[i] = make_float4(0.f, 0.f, 0.f, 0.f);
        g_cpcnt[i] = 0; g_fi[i] = INT_MAX; g_cpbeta[i] = 0.f;
    }
    if (idx < BB) { g_ncp[idx] = 0; g_nbg[idx] = 0; g_bgsig[idx] = 0.f; g_rep[idx] = 0.f; }
    if (idx < 8) g_bar[idx] = 0u;
}

// ---------------- software grid barrier (all NB blocks co-resident) ----------------
__device__ __forceinline__ void gsync(int id) {
    __syncthreads();
    if (threadIdx.x == 0) {
        __threadfence();
        atomicAdd((unsigned*)&g_bar[id], 1u);
        while (g_bar[id] < (unsigned)NB) { }
        __threadfence();
    }
    __syncthreads();
}

__device__ __forceinline__ float dist16(float4 a0, float4 a1, float4 a2, float4 a3,
                                        float4 b0, float4 b1, float4 b2, float4 b3) {
    float d = 0.f, df;
    df = a0.x-b0.x; d += df*df; df = a0.y-b0.y; d += df*df;
    df = a0.z-b0.z; d += df*df; df = a0.w-b0.w; d += df*df;
    df = a1.x-b1.x; d += df*df; df = a1.y-b1.y; d += df*df;
    df = a1.z-b1.z; d += df*df; df = a1.w-b1.w; d += df*df;
    df = a2.x-b2.x; d += df*df; df = a2.y-b2.y; d += df*df;
    df = a2.z-b2.z; d += df*df; df = a2.w-b2.w; d += df*df;
    df = a3.x-b3.x; d += df*df; df = a3.y-b3.y; d += df*df;
    df = a3.z-b3.z; d += df*df; df = a3.w-b3.w; d += df*df;
    return d;
}

// ---------------- launch 2: persistent mega-kernel ----------------
__global__ void __launch_bounds__(NT, 1)
mega_kernel(const float* __restrict__ beta, const float* __restrict__ embed,
            const int* __restrict__ sid, const int* __restrict__ iscp,
            float* __restrict__ out, int out_size, int N) {
    int bx = blockIdx.x, t = threadIdx.x;
    int gt = bx * NT + t;
    const int G = NB * NT;

    __shared__ float4 s_tab[KK*4];   // 32 KB: ref table (phase C) then cp table (rep)
    __shared__ float  s_red[16];

    // ===== Phase A: light-array stats (sid/iscp int4 stream; beta only when needed) =====
    for (int b = 0; b < BB; b++) {
        const int4*   s4p = (const int4*)(sid  + (size_t)b * N);
        const int4*   c4p = (const int4*)(iscp + (size_t)b * N);
        const float4* b4p = (const float4*)(beta + (size_t)b * N);
        float bgs = 0.f; int bgc = 0;
        int NG = N >> 2;
        for (int j = gt; j < NG; j += G) {
            int4 s4 = s4p[j]; int4 c4 = c4p[j];
            bool anybg = ((s4.x | s4.y | s4.z | s4.w) < 0);
            bool anycp = ((c4.x | c4.y | c4.z | c4.w) != 0);
            if (anybg | anycp) {
                float4 bt = b4p[j];
                int bi = j << 2;
                int   ss[4] = { s4.x, s4.y, s4.z, s4.w };
                int   cc[4] = { c4.x, c4.y, c4.z, c4.w };
                float bb4[4] = { bt.x, bt.y, bt.z, bt.w };
                #pragma unroll
                for (int e = 0; e < 4; e++) {
                    int s = ss[e];
                    if (s < 0) { bgc++; bgs += 1.f / (1.f + __expf(-bb4[e])); }
                    if (cc[e] == 1) {
                        if (s >= 0) {
                            int gi = b*KK + s;
                            atomicAdd(&g_cpcnt[gi], 1);
                            atomicAdd(&g_cpbeta[gi], bb4[e]);
                            atomicMin(&g_fi[gi], bi + e);
                        }
                        int pos = atomicAdd(&g_ncp[b], 1);
                        if (pos < CPBUF) g_cpidx[b*CPBUF + pos] = bi + e;
                    }
                }
            }
        }
        // tail (N % 4)
        for (int i = (NG << 2) + gt; i < N; i += G) {
            int s = sid[(size_t)b*N + i];
            int c = iscp[(size_t)b*N + i];
            if ((s < 0) | (c != 0)) {
                float bt = beta[(size_t)b*N + i];
                if (s < 0) { bgc++; bgs += 1.f / (1.f + __expf(-bt)); }
                if (c == 1) {
                    if (s >= 0) {
                        int gi = b*KK + s;
                        atomicAdd(&g_cpcnt[gi], 1);
                        atomicAdd(&g_cpbeta[gi], bt);
                        atomicMin(&g_fi[gi], i);
                    }
                    int pos = atomicAdd(&g_ncp[b], 1);
                    if (pos < CPBUF) g_cpidx[b*CPBUF + pos] = i;
                }
            }
        }
        for (int o = 16; o > 0; o >>= 1) {
            bgs += __shfl_down_sync(0xffffffffu, bgs, o);
            bgc += __shfl_down_sync(0xffffffffu, bgc, o);
        }
        if ((t & 31) == 0 && bgc > 0) {
            atomicAdd(&g_bgsig[b], bgs);
            atomicAdd(&g_nbg[b], bgc);
        }
    }
    gsync(0);

    // ===== Phase B: gather reference embeddings =====
    if (gt < BB*KK*4) {
        int gi = gt >> 2, comp = gt & 3;
        int b = gi >> 9;
        int fi = g_fi[gi];
        float4 v = make_float4(0.f, 0.f, 0.f, 0.f);
        if (g_cpcnt[gi] >= 1 && fi != INT_MAX)
            v = ((const float4*)(embed + (size_t)b*N*DD + (size_t)fi*DD))[comp];
        ((float4*)g_ref)[gi*4 + comp] = v;
    }
    gsync(1);

    // ===== Phase C: main embed stream (unroll-2 for MLP) =====
    {
        int b    = bx & 7;
        int rank = bx >> 3;
        int nbb  = (b < 4) ? 19 : 18;   // 148 = 8*18 + 4
        const float4* gr = (const float4*)&g_ref[(size_t)b*KK*DD];
        for (int k = t; k < KK*4; k += NT) s_tab[k] = gr[k];
        __syncthreads();

        const float*  betB = beta  + (size_t)b * N;
        const float*  embB = embed + (size_t)b * N * DD;
        const int*    sidB = sid   + (size_t)b * N;
        float4* accB = &g_acc[b*KK];

        int S = nbb * NT;
        int i = rank * NT + t;
        for (; i + S < N; i += 2*S) {
            int   s0 = sidB[i],  s1 = sidB[i + S];
            float bt0 = betB[i], bt1 = betB[i + S];
            const float4* p0 = (const float4*)(embB + (size_t)i * DD);
            const float4* p1 = (const float4*)(embB + (size_t)(i + S) * DD);
            float4 a0 = p0[0], a1 = p0[1], a2 = p0[2], a3 = p0[3];
            float4 c0 = p1[0], c1 = p1[1], c2 = p1[2], c3 = p1[3];
            if (s0 >= 0) {
                float4 r0 = s_tab[s0*4+0], r1 = s_tab[s0*4+1], r2 = s_tab[s0*4+2], r3 = s_tab[s0*4+3];
                float d = dist16(a0, a1, a2, a3, r0, r1, r2, r3);
                atomicAdd(&accB[s0], make_float4(1.f, __expf(bt0), d, 0.f));
            }
            if (s1 >= 0) {
                float4 r0 = s_tab[s1*4+0], r1 = s_tab[s1*4+1], r2 = s_tab[s1*4+2], r3 = s_tab[s1*4+3];
                float d = dist16(c0, c1, c2, c3, r0, r1, r2, r3);
                atomicAdd(&accB[s1], make_float4(1.f, __expf(bt1), d, 0.f));
            }
        }
        for (; i < N; i += S) {
            int s0 = sidB[i];
            if (s0 >= 0) {
                float bt0 = betB[i];
                const float4* p0 = (const float4*)(embB + (size_t)i * DD);
                float4 a0 = p0[0], a1 = p0[1], a2 = p0[2], a3 = p0[3];
                float4 r0 = s_tab[s0*4+0], r1 = s_tab[s0*4+1], r2 = s_tab[s0*4+2], r3 = s_tab[s0*4+3];
                float d = dist16(a0, a1, a2, a3, r0, r1, r2, r3);
                atomicAdd(&accB[s0], make_float4(1.f, __expf(bt0), d, 0.f));
            }
        }
    }

    // ===== Repulsion (overlapped; depends only on phases A/B) =====
    __syncthreads();   // block-local: done with ref table
    if (bx < 128) {
        int rb   = bx >> 4;   // batch
        int tile = bx & 15;   // i-tile (32 rows each)
        int P = g_ncp[rb]; if (P > MAX_CPN) P = MAX_CPN;
        const float4* embB = (const float4*)(embed + (size_t)rb * N * DD);
        for (int k = t; k < KK*4; k += NT) {
            int jj = k >> 2;
            float4 v = make_float4(0.f, 0.f, 0.f, 0.f);
            if (jj < P) v = embB[(size_t)g_cpidx[rb*CPBUF + jj] * 4 + (k & 3)];
            s_tab[k] = v;
        }
        __syncthreads();

        int il    = tile * 32 + (t >> 4);
        int strip = t & 15;
        float acc = 0.f;
        if (il < P) {
            float4 a0 = s_tab[il*4+0], a1 = s_tab[il*4+1], a2 = s_tab[il*4+2], a3 = s_tab[il*4+3];
            int j0 = strip * 32;
            #pragma unroll 4
            for (int jj = j0; jj < j0 + 32; jj++) {
                if (jj < P) {
                    float d = dist16(a0, a1, a2, a3,
                                     s_tab[jj*4+0], s_tab[jj*4+1], s_tab[jj*4+2], s_tab[jj*4+3]);
                    if (d < 30.f) acc += __expf(-d);   // exp(-30)~9e-14: negligible
                }
            }
        }
        for (int o = 16; o > 0; o >>= 1) acc += __shfl_down_sync(0xffffffffu, acc, o);
        if ((t & 31) == 0) s_red[t >> 5] = acc;
        __syncthreads();
        if (t < 16) {
            float v = s_red[t];
            for (int o = 8; o > 0; o >>= 1) v += __shfl_down_sync(0xffffu, v, o);
            if (t == 0) atomicAdd(&g_rep[rb], v);
        }
    }
    gsync(2);

    // ===== Finalize + output (block 0 only) =====
    if (bx == 0) {
        __shared__ float s_ce[BB], s_at[BB];
        __shared__ int   s_vl[BB];
        __shared__ float s_o[5];
        if (t < BB) { s_ce[t] = 0.f; s_at[t] = 0.f; s_vl[t] = 0; }
        __syncthreads();
        for (int gi = t; gi < BB*KK; gi += NT) {
            float4 a = g_acc[gi];
            int cpc = g_cpcnt[gi];
            int b = gi >> 9;
            if (a.x > 0.f && cpc == 1) {
                atomicAdd(&s_ce[b], __logf(fmaxf(a.y, 1e-30f)) - g_cpbeta[gi]);
                atomicAdd(&s_vl[b], 1);
            }
            if (a.x > 0.f && cpc >= 1)
                atomicAdd(&s_at[b], a.z / fmaxf(a.x, 1.f));
        }
        __syncthreads();
        __shared__ float s_b[BB][5];
        if (t < BB) {
            int b = t;
            int sc = s_vl[b];
            float bl = s_ce[b] / fmaxf((float)sc, 1.f);
            int nbg = g_nbg[b];
            if (nbg > 0) bl += BG_W * (g_bgsig[b] / (float)nbg);
            float attr = s_at[b];
            int ncp = g_ncp[b];
            float rep = (ncp > 1) ? g_rep[b] / fmaxf((float)ncp * (float)ncp, 1.f) : 0.f;
            s_b[b][0] = bl + attr + rep;
            s_b[b][1] = bl;
            s_b[b][2] = attr;
            s_b[b][3] = rep;
            s_b[b][4] = (sc > 0) ? 1.f : 0.f;
        }
        __syncthreads();
        if (t == 0) {
            float cnt = 0.f, t0 = 0.f, t1 = 0.f, t2 = 0.f, t3 = 0.f;
            for (int b = 0; b < BB; b++) {
                float inc = s_b[b][4];
                cnt += inc;
                t0 += s_b[b][0] * inc;
                t1 += s_b[b][1] * inc;
                t2 += s_b[b][2] * inc;
                t3 += s_b[b][3] * inc;
            }
            float den = fmaxf(cnt, 1.f);
            s_o[0] = (cnt > 0.f) ? t0 / den : 0.f;
            s_o[1] = t1 / den; s_o[2] = t2 / den; s_o[3] = t3 / den;
            if (out_size > 0) out[0] = s_o[0];
            if (out_size > 1) out[1] = s_o[1];
            if (out_size > 2) out[2] = s_o[2];
            if (out_size > 3) out[3] = s_o[3];
        }
    }
}

extern "C" void kernel_launch(void* const* d_in, const int* in_sizes, int n_in,
                              void* d_out, int out_size) {
    const float* beta  = (const float*)d_in[0];
    const float* embed = (const float*)d_in[1];
    const int*   sid   = (const int*)d_in[2];
    const int*   iscp  = (const int*)d_in[3];
    int N = in_sizes[0] / BB;

    zero_kernel<<<32, 256>>>();
    mega_kernel<<<NB, NT>>>(beta, embed, sid, iscp, (float*)d_out, out_size, N);
}

// round 4
// speedup vs baseline: 1.0974x; 1.0974x over previous
#include <cuda_runtime.h>
#include <math.h>
#include <limits.h>
#include <stdint.h>

#define BB 8
#define KK 512
#define DD 16
#define MAX_CPN 512
#define CPBUF 1024
#define BG_W 2.0f

#define TPB 256
#define PPC 2048

// ---------------- device scratch ----------------
__device__ float4 g_acc[BB*KK];        // {cnt, sumexp, dsum, pad}
__device__ int    g_cpcnt[BB*KK];
__device__ int    g_fi[BB*KK];
__device__ float  g_cpbeta[BB*KK];
__device__ float  g_ref[BB*KK*DD];
__device__ int    g_ncp[BB];
__device__ int    g_nbg[BB];
__device__ float  g_bgsig[BB];
__device__ int    g_cpidx[BB*CPBUF];
__device__ float  g_rep[BB];

__device__ __forceinline__ float dist16(float4 a0, float4 a1, float4 a2, float4 a3,
                                        float4 b0, float4 b1, float4 b2, float4 b3) {
    float d = 0.f, df;
    df = a0.x-b0.x; d += df*df; df = a0.y-b0.y; d += df*df;
    df = a0.z-b0.z; d += df*df; df = a0.w-b0.w; d += df*df;
    df = a1.x-b1.x; d += df*df; df = a1.y-b1.y; d += df*df;
    df = a1.z-b1.z; d += df*df; df = a1.w-b1.w; d += df*df;
    df = a2.x-b2.x; d += df*df; df = a2.y-b2.y; d += df*df;
    df = a2.z-b2.z; d += df*df; df = a2.w-b2.w; d += df*df;
    df = a3.x-b3.x; d += df*df; df = a3.y-b3.y; d += df*df;
    df = a3.z-b3.z; d += df*df; df = a3.w-b3.w; d += df*df;
    return d;
}

// ---------------- zero ----------------
__global__ void zero_kernel() {
    int idx = blockIdx.x * blockDim.x + threadIdx.x;
    int stride = gridDim.x * blockDim.x;
    for (int i = idx; i < BB*KK; i += stride) {
        g_acc[i] = make_float4(0.f, 0.f, 0.f, 0.f);
        g_cpcnt[i] = 0; g_fi[i] = INT_MAX; g_cpbeta[i] = 0.f;
    }
    if (idx < BB) { g_ncp[idx] = 0; g_nbg[idx] = 0; g_bgsig[idx] = 0.f; g_rep[idx] = 0.f; }
}

// ---------------- pass A: vectorized light-array stats ----------------
__global__ void __launch_bounds__(TPB)
pass_a(const float* __restrict__ beta, const int* __restrict__ sid,
       const int* __restrict__ iscp, int N) {
    int b = blockIdx.y;
    const int4*   s4p = (const int4*)(sid  + (size_t)b * N);
    const int4*   c4p = (const int4*)(iscp + (size_t)b * N);
    const float4* b4p = (const float4*)(beta + (size_t)b * N);
    int NG = N >> 2;
    int gt = blockIdx.x * TPB + threadIdx.x;
    int G  = gridDim.x * TPB;
    float bgs = 0.f; int bgc = 0;

    for (int j = gt; j < NG; j += G) {
        int4   s4 = s4p[j];
        int4   c4 = c4p[j];
        float4 bt = b4p[j];
        int   ss[4] = { s4.x, s4.y, s4.z, s4.w };
        int   cc[4] = { c4.x, c4.y, c4.z, c4.w };
        float bv[4] = { bt.x, bt.y, bt.z, bt.w };
        int bi = j << 2;
        #pragma unroll
        for (int e = 0; e < 4; e++) {
            int s = ss[e];
            if (s < 0) { bgc++; bgs += 1.f / (1.f + __expf(-bv[e])); }
            if (cc[e] == 1) {
                if (s >= 0) {
                    int gi = b*KK + s;
                    atomicAdd(&g_cpcnt[gi], 1);
                    atomicAdd(&g_cpbeta[gi], bv[e]);
                    atomicMin(&g_fi[gi], bi + e);
                }
                int pos = atomicAdd(&g_ncp[b], 1);
                if (pos < CPBUF) g_cpidx[b*CPBUF + pos] = bi + e;
            }
        }
    }
    // tail
    for (int i = (NG << 2) + gt; i < N; i += G) {
        int s = sid[(size_t)b*N + i];
        int c = iscp[(size_t)b*N + i];
        float btv = beta[(size_t)b*N + i];
        if (s < 0) { bgc++; bgs += 1.f / (1.f + __expf(-btv)); }
        if (c == 1) {
            if (s >= 0) {
                int gi = b*KK + s;
                atomicAdd(&g_cpcnt[gi], 1);
                atomicAdd(&g_cpbeta[gi], btv);
                atomicMin(&g_fi[gi], i);
            }
            int pos = atomicAdd(&g_ncp[b], 1);
            if (pos < CPBUF) g_cpidx[b*CPBUF + pos] = i;
        }
    }
    for (int o = 16; o > 0; o >>= 1) {
        bgs += __shfl_down_sync(0xffffffffu, bgs, o);
        bgc += __shfl_down_sync(0xffffffffu, bgc, o);
    }
    if ((threadIdx.x & 31) == 0 && bgc > 0) {
        atomicAdd(&g_bgsig[b], bgs);
        atomicAdd(&g_nbg[b], bgc);
    }
}

// ---------------- pass B: gather reference embeddings ----------------
__global__ void __launch_bounds__(512)
gather_ref(const float* __restrict__ embed, int N) {
    int gt = blockIdx.x * 512 + threadIdx.x;
    if (gt >= BB*KK*4) return;
    int gi = gt >> 2, comp = gt & 3;
    int b = gi >> 9;
    int fi = g_fi[gi];
    float4 v = make_float4(0.f, 0.f, 0.f, 0.f);
    if (g_cpcnt[gi] >= 1 && fi != INT_MAX)
        v = ((const float4*)(embed + (size_t)b*N*DD + (size_t)fi*DD))[comp];
    ((float4*)g_ref)[gi*4 + comp] = v;
}

// ---------------- pass C: embed stream, branch-free, unroll-2 ----------------
__global__ void __launch_bounds__(TPB)
pass_c(const float* __restrict__ beta, const float* __restrict__ embed,
       const int* __restrict__ sid, int N) {
    __shared__ float4 s_ref[KK*4];
    int b = blockIdx.y;
    int t = threadIdx.x;
    const float4* gr = (const float4*)&g_ref[(size_t)b*KK*DD];
    for (int k = t; k < KK*4; k += TPB) s_ref[k] = gr[k];
    __syncthreads();

    const float* betB = beta  + (size_t)b * N;
    const float* embB = embed + (size_t)b * N * DD;
    const int*   sidB = sid   + (size_t)b * N;
    float4* accB = &g_acc[b*KK];

    int base = blockIdx.x * PPC;
    int end  = min(base + PPC, N);

    int i = base + t;
    for (; i + TPB < end; i += 2*TPB) {
        int   s0  = sidB[i];
        int   s1  = sidB[i + TPB];
        float bt0 = betB[i];
        float bt1 = betB[i + TPB];
        const float4* p0 = (const float4*)(embB + (size_t)i * DD);
        const float4* p1 = (const float4*)(embB + (size_t)(i + TPB) * DD);
        float4 a0 = p0[0], a1 = p0[1], a2 = p0[2], a3 = p0[3];
        float4 c0 = p1[0], c1 = p1[1], c2 = p1[2], c3 = p1[3];
        int u0 = max(s0, 0) * 4;
        int u1 = max(s1, 0) * 4;
        float d0 = dist16(a0, a1, a2, a3, s_ref[u0+0], s_ref[u0+1], s_ref[u0+2], s_ref[u0+3]);
        float d1 = dist16(c0, c1, c2, c3, s_ref[u1+0], s_ref[u1+1], s_ref[u1+2], s_ref[u1+3]);
        float e0 = __expf(bt0);
        float e1 = __expf(bt1);
        if (s0 >= 0) atomicAdd(&accB[s0], make_float4(1.f, e0, d0, 0.f));
        if (s1 >= 0) atomicAdd(&accB[s1], make_float4(1.f, e1, d1, 0.f));
    }
    for (; i < end; i += TPB) {
        int s0 = sidB[i];
        float bt0 = betB[i];
        const float4* p0 = (const float4*)(embB + (size_t)i * DD);
        float4 a0 = p0[0], a1 = p0[1], a2 = p0[2], a3 = p0[3];
        int u0 = max(s0, 0) * 4;
        float d0 = dist16(a0, a1, a2, a3, s_ref[u0+0], s_ref[u0+1], s_ref[u0+2], s_ref[u0+3]);
        if (s0 >= 0) atomicAdd(&accB[s0], make_float4(1.f, __expf(bt0), d0, 0.f));
    }
}

// ---------------- repulsion ----------------
__global__ void __launch_bounds__(256)
rep_kernel(const float* __restrict__ embed, int N) {
    int b = blockIdx.x;
    int P = g_ncp[b]; if (P > MAX_CPN) P = MAX_CPN;
    int t = threadIdx.x;

    __shared__ float4 s_e[KK*4];
    const float4* embB = (const float4*)(embed + (size_t)b*N*DD);
    for (int k = t; k < KK*4; k += 256) {
        int jj = k >> 2;
        float4 v = make_float4(0.f, 0.f, 0.f, 0.f);
        if (jj < P) v = embB[(size_t)g_cpidx[b*CPBUF + jj] * 4 + (k & 3)];
        s_e[k] = v;
    }
    __syncthreads();

    int il    = blockIdx.y * 32 + (t >> 3);   // 32 i-rows per block, 16 y-blocks
    int strip = t & 7;
    float acc = 0.f;
    if (il < P) {
        float4 a0 = s_e[il*4+0], a1 = s_e[il*4+1], a2 = s_e[il*4+2], a3 = s_e[il*4+3];
        int j0 = strip * 64;
        #pragma unroll 4
        for (int jj = j0; jj < j0 + 64; jj++) {
            if (jj < P) {
                float d = dist16(a0, a1, a2, a3,
                                 s_e[jj*4+0], s_e[jj*4+1], s_e[jj*4+2], s_e[jj*4+3]);
                if (d < 30.f) acc += __expf(-d);   // exp(-30)~9e-14: negligible
            }
        }
    }
    for (int o = 16; o > 0; o >>= 1) acc += __shfl_down_sync(0xffffffffu, acc, o);
    __shared__ float wsum[8];
    if ((t & 31) == 0) wsum[t >> 5] = acc;
    __syncthreads();
    if (t < 8) {
        float v = wsum[t];
        for (int o = 4; o > 0; o >>= 1) v += __shfl_down_sync(0xffu, v, o);
        if (t == 0) atomicAdd(&g_rep[b], v);
    }
}

// ---------------- finalize + output (single block) ----------------
__global__ void __launch_bounds__(512)
finalize_kernel(float* __restrict__ out, int out_size) {
    int t = threadIdx.x;
    __shared__ float s_ce[BB], s_at[BB];
    __shared__ int   s_vl[BB];
    if (t < BB) { s_ce[t] = 0.f; s_at[t] = 0.f; s_vl[t] = 0; }
    __syncthreads();
    for (int gi = t; gi < BB*KK; gi += 512) {
        float4 a = g_acc[gi];
        int cpc = g_cpcnt[gi];
        int b = gi >> 9;
        if (a.x > 0.f && cpc == 1) {
            atomicAdd(&s_ce[b], __logf(fmaxf(a.y, 1e-30f)) - g_cpbeta[gi]);
            atomicAdd(&s_vl[b], 1);
        }
        if (a.x > 0.f && cpc >= 1)
            atomicAdd(&s_at[b], a.z / fmaxf(a.x, 1.f));
    }
    __syncthreads();
    __shared__ float s_b[BB][5];
    if (t < BB) {
        int b = t;
        int sc = s_vl[b];
        float bl = s_ce[b] / fmaxf((float)sc, 1.f);
        int nbg = g_nbg[b];
        if (nbg > 0) bl += BG_W * (g_bgsig[b] / (float)nbg);
        float attr = s_at[b];
        int ncp = g_ncp[b];
        float rep = (ncp > 1) ? g_rep[b] / fmaxf((float)ncp * (float)ncp, 1.f) : 0.f;
        s_b[b][0] = bl + attr + rep;
        s_b[b][1] = bl;
        s_b[b][2] = attr;
        s_b[b][3] = rep;
        s_b[b][4] = (sc > 0) ? 1.f : 0.f;
    }
    __syncthreads();
    if (t == 0) {
        float cnt = 0.f, t0 = 0.f, t1 = 0.f, t2 = 0.f, t3 = 0.f;
        for (int b = 0; b < BB; b++) {
            float inc = s_b[b][4];
            cnt += inc;
            t0 += s_b[b][0] * inc;
            t1 += s_b[b][1] * inc;
            t2 += s_b[b][2] * inc;
            t3 += s_b[b][3] * inc;
        }
        float den = fmaxf(cnt, 1.f);
        if (out_size > 0) out[0] = (cnt > 0.f) ? t0 / den : 0.f;
        if (out_size > 1) out[1] = t1 / den;
        if (out_size > 2) out[2] = t2 / den;
        if (out_size > 3) out[3] = t3 / den;
    }
}

extern "C" void kernel_launch(void* const* d_in, const int* in_sizes, int n_in,
                              void* d_out, int out_size) {
    const float* beta  = (const float*)d_in[0];
    const float* embed = (const float*)d_in[1];
    const int*   sid   = (const int*)d_in[2];
    const int*   iscp  = (const int*)d_in[3];
    int N = in_sizes[0] / BB;

    zero_kernel<<<32, 256>>>();
    dim3 ga(64, BB);
    pass_a<<<ga, TPB>>>(beta, sid, iscp, N);
    gather_ref<<<(BB*KK*4 + 511) / 512, 512>>>(embed, N);
    dim3 gc((N + PPC - 1) / PPC, BB);
    pass_c<<<gc, TPB>>>(beta, embed, sid, N);
    dim3 gr(BB, 16);
    rep_kernel<<<gr, 256>>>(embed, N);
    finalize_kernel<<<1, 512>>>((float*)d_out, out_size);
}

// round 5
// speedup vs baseline: 1.2388x; 1.1289x over previous
#include <cuda_runtime.h>
#include <math.h>
#include <limits.h>
#include <stdint.h>

#define BB 8
#define KK 512
#define DD 16
#define MAX_CPN 512
#define CPBUF 1024
#define BG_W 2.0f

#define TPB 256
#define PPC 2048
#define UC 4

// ---------------- device scratch (all-zero == clean state; finalize re-zeros) ----------------
__device__ float4 g_acc[BB*KK];        // {cnt, sumexp, dsum, pad}
__device__ int    g_cpcnt[BB*KK];
__device__ int    g_fimax[BB*KK];      // 0 = none, else (N - first_cp_index)
__device__ float  g_cpbeta[BB*KK];
__device__ float  g_ref[BB*KK*DD];
__device__ int    g_ncp[BB];
__device__ int    g_nbg[BB];
__device__ float  g_bgsig[BB];
__device__ int    g_cpidx[BB*CPBUF];
__device__ float  g_rep[BB];

__device__ __forceinline__ float dist16(float4 a0, float4 a1, float4 a2, float4 a3,
                                        float4 b0, float4 b1, float4 b2, float4 b3) {
    float d = 0.f, df;
    df = a0.x-b0.x; d += df*df; df = a0.y-b0.y; d += df*df;
    df = a0.z-b0.z; d += df*df; df = a0.w-b0.w; d += df*df;
    df = a1.x-b1.x; d += df*df; df = a1.y-b1.y; d += df*df;
    df = a1.z-b1.z; d += df*df; df = a1.w-b1.w; d += df*df;
    df = a2.x-b2.x; d += df*df; df = a2.y-b2.y; d += df*df;
    df = a2.z-b2.z; d += df*df; df = a2.w-b2.w; d += df*df;
    df = a3.x-b3.x; d += df*df; df = a3.y-b3.y; d += df*df;
    df = a3.z-b3.z; d += df*df; df = a3.w-b3.w; d += df*df;
    return d;
}

// ---------------- pass A: light-array stats (int4/float4 vectorized) ----------------
__global__ void __launch_bounds__(TPB)
pass_a(const float* __restrict__ beta, const int* __restrict__ sid,
       const int* __restrict__ iscp, int N) {
    int b = blockIdx.y;
    const int4*   s4p = (const int4*)(sid  + (size_t)b * N);
    const int4*   c4p = (const int4*)(iscp + (size_t)b * N);
    const float4* b4p = (const float4*)(beta + (size_t)b * N);
    int NG = N >> 2;
    int gt = blockIdx.x * TPB + threadIdx.x;
    int G  = gridDim.x * TPB;
    float bgs = 0.f; int bgc = 0;

    for (int j = gt; j < NG; j += G) {
        int4   s4 = s4p[j];
        int4   c4 = c4p[j];
        float4 bt = b4p[j];
        int   ss[4] = { s4.x, s4.y, s4.z, s4.w };
        int   cc[4] = { c4.x, c4.y, c4.z, c4.w };
        float bv[4] = { bt.x, bt.y, bt.z, bt.w };
        int bi = j << 2;
        #pragma unroll
        for (int e = 0; e < 4; e++) {
            int s = ss[e];
            if (s < 0) { bgc++; bgs += 1.f / (1.f + __expf(-bv[e])); }
            if (cc[e] == 1) {
                if (s >= 0) {
                    int gi = b*KK + s;
                    atomicAdd(&g_cpcnt[gi], 1);
                    atomicAdd(&g_cpbeta[gi], bv[e]);
                    atomicMax(&g_fimax[gi], N - (bi + e));
                }
                int pos = atomicAdd(&g_ncp[b], 1);
                if (pos < CPBUF) g_cpidx[b*CPBUF + pos] = bi + e;
            }
        }
    }
    for (int i = (NG << 2) + gt; i < N; i += G) {   // tail
        int s = sid[(size_t)b*N + i];
        int c = iscp[(size_t)b*N + i];
        float btv = beta[(size_t)b*N + i];
        if (s < 0) { bgc++; bgs += 1.f / (1.f + __expf(-btv)); }
        if (c == 1) {
            if (s >= 0) {
                int gi = b*KK + s;
                atomicAdd(&g_cpcnt[gi], 1);
                atomicAdd(&g_cpbeta[gi], btv);
                atomicMax(&g_fimax[gi], N - i);
            }
            int pos = atomicAdd(&g_ncp[b], 1);
            if (pos < CPBUF) g_cpidx[b*CPBUF + pos] = i;
        }
    }
    for (int o = 16; o > 0; o >>= 1) {
        bgs += __shfl_down_sync(0xffffffffu, bgs, o);
        bgc += __shfl_down_sync(0xffffffffu, bgc, o);
    }
    if ((threadIdx.x & 31) == 0 && bgc > 0) {
        atomicAdd(&g_bgsig[b], bgs);
        atomicAdd(&g_nbg[b], bgc);
    }
}

// ---------------- pass B: gather reference embeddings ----------------
__global__ void __launch_bounds__(512)
gather_ref(const float* __restrict__ embed, int N) {
    int gt = blockIdx.x * 512 + threadIdx.x;
    if (gt >= BB*KK*4) return;
    int gi = gt >> 2, comp = gt & 3;
    int b = gi >> 9;
    int fm = g_fimax[gi];
    float4 v = make_float4(0.f, 0.f, 0.f, 0.f);
    if (g_cpcnt[gi] >= 1 && fm > 0) {
        int fi = N - fm;
        v = ((const float4*)(embed + (size_t)b*N*DD + (size_t)fi*DD))[comp];
    }
    ((float4*)g_ref)[gi*4 + comp] = v;
}

// ---------------- pass C (quad-split, coalesced) + fused repulsion blocks ----------------
__global__ void __launch_bounds__(TPB)
pass_c(const float* __restrict__ beta, const float* __restrict__ embed,
       const int* __restrict__ sid, int N, int NC) {
    __shared__ float4 s_tab[KK*4];   // 32 KB
    int b = blockIdx.y;
    int t = threadIdx.x;

    if (blockIdx.x < NC) {
        // ----- main embed stream -----
        const float4* gr = (const float4*)&g_ref[(size_t)b*KK*DD];
        for (int k = t; k < KK*4; k += TPB) s_tab[k] = gr[k];
        __syncthreads();

        const float*  betB = beta  + (size_t)b * N;
        const float*  embB = embed + (size_t)b * N * DD;
        const int*    sidB = sid   + (size_t)b * N;
        const float4* ef4  = (const float4*)embB;
        float4* accB = &g_acc[b*KK];

        int base = blockIdx.x * PPC;
        int end  = min(base + PPC, N);
        int q = t >> 2;       // point-in-group 0..63
        int c = t & 3;        // component quad lane

        for (int i0 = base + q; i0 < end; i0 += 64 * UC) {
            int   s[UC]; float bt[UC]; float4 e[UC];
            #pragma unroll
            for (int u = 0; u < UC; u++) {
                int i = i0 + u * 64;
                bool act = i < end;
                s[u]  = act ? sidB[i] : -1;
                bt[u] = act ? betB[i] : 0.f;
                e[u]  = act ? ef4[(size_t)i * 4 + c] : make_float4(0.f,0.f,0.f,0.f);
            }
            #pragma unroll
            for (int u = 0; u < UC; u++) {
                int ui = max(s[u], 0);
                float4 r = s_tab[(ui << 2) | c];
                float df, pd = 0.f;
                df = e[u].x - r.x; pd += df*df;
                df = e[u].y - r.y; pd += df*df;
                df = e[u].z - r.z; pd += df*df;
                df = e[u].w - r.w; pd += df*df;
                pd += __shfl_xor_sync(0xffffffffu, pd, 1);
                pd += __shfl_xor_sync(0xffffffffu, pd, 2);
                if (c == 0 && s[u] >= 0) {
                    int i = i0 + u * 64;
                    atomicAdd(&accB[s[u]], make_float4(1.f, __expf(bt[u]), pd, 0.f));
                }
            }
        }
    } else {
        // ----- repulsion: 2 blocks per batch, warp-broadcast j-loop -----
        int half = blockIdx.x - NC;   // 0 or 1
        int P = g_ncp[b]; if (P > MAX_CPN) P = MAX_CPN;
        const float4* embB = (const float4*)(embed + (size_t)b * N * DD);
        for (int k = t; k < KK*4; k += TPB) {
            int jj = k >> 2;
            float4 v = make_float4(0.f, 0.f, 0.f, 0.f);
            if (jj < P) v = embB[(size_t)g_cpidx[b*CPBUF + jj] * 4 + (k & 3)];
            s_tab[k] = v;
        }
        __syncthreads();

        int i = half * 256 + t;
        float acc = 0.f;
        if (i < P) {
            float4 a0 = s_tab[i*4+0], a1 = s_tab[i*4+1], a2 = s_tab[i*4+2], a3 = s_tab[i*4+3];
            #pragma unroll 2
            for (int j = 0; j < P; j++) {
                float d = dist16(a0, a1, a2, a3,
                                 s_tab[j*4+0], s_tab[j*4+1], s_tab[j*4+2], s_tab[j*4+3]);
                if (d < 30.f) acc += __expf(-d);   // exp(-30)~9e-14 negligible
            }
        }
        for (int o = 16; o > 0; o >>= 1) acc += __shfl_down_sync(0xffffffffu, acc, o);
        __shared__ float wsum[8];
        if ((t & 31) == 0) wsum[t >> 5] = acc;
        __syncthreads();
        if (t < 8) {
            float v = wsum[t];
            for (int o = 4; o > 0; o >>= 1) v += __shfl_down_sync(0xffu, v, o);
            if (t == 0 && v != 0.f) atomicAdd(&g_rep[b], v);
        }
    }
}

// ---------------- finalize + output + scratch reset (single block) ----------------
__global__ void __launch_bounds__(512)
finalize_kernel(float* __restrict__ out, int out_size) {
    int t = threadIdx.x;
    __shared__ float s_ce[BB], s_at[BB];
    __shared__ int   s_vl[BB];
    __shared__ float s_sc[BB][4];   // ncp, nbg, bgsig, rep snapshots
    if (t < BB) { s_ce[t] = 0.f; s_at[t] = 0.f; s_vl[t] = 0; }
    __syncthreads();
    for (int gi = t; gi < BB*KK; gi += 512) {
        float4 a = g_acc[gi];
        int cpc = g_cpcnt[gi];
        float cpb = g_cpbeta[gi];
        int b = gi >> 9;
        if (a.x > 0.f && cpc == 1) {
            atomicAdd(&s_ce[b], __logf(fmaxf(a.y, 1e-30f)) - cpb);
            atomicAdd(&s_vl[b], 1);
        }
        if (a.x > 0.f && cpc >= 1)
            atomicAdd(&s_at[b], a.z / fmaxf(a.x, 1.f));
        // reset for next graph replay
        g_acc[gi] = make_float4(0.f, 0.f, 0.f, 0.f);
        g_cpcnt[gi] = 0; g_cpbeta[gi] = 0.f; g_fimax[gi] = 0;
    }
    if (t < BB) {
        s_sc[t][0] = (float)g_ncp[t];
        s_sc[t][1] = (float)g_nbg[t];
        s_sc[t][2] = g_bgsig[t];
        s_sc[t][3] = g_rep[t];
        g_ncp[t] = 0; g_nbg[t] = 0; g_bgsig[t] = 0.f; g_rep[t] = 0.f;
    }
    __syncthreads();
    if (t == 0) {
        float cnt = 0.f, t0 = 0.f, t1 = 0.f, t2 = 0.f, t3 = 0.f;
        for (int b = 0; b < BB; b++) {
            int sc = s_vl[b];
            float bl = s_ce[b] / fmaxf((float)sc, 1.f);
            float nbg = s_sc[b][1];
            if (nbg > 0.f) bl += BG_W * (s_sc[b][2] / nbg);
            float attr = s_at[b];
            float ncp = s_sc[b][0];
            float rep = (ncp > 1.f) ? s_sc[b][3] / fmaxf(ncp * ncp, 1.f) : 0.f;
            float inc = (sc > 0) ? 1.f : 0.f;
            cnt += inc;
            t0 += (bl + attr + rep) * inc;
            t1 += bl * inc;
            t2 += attr * inc;
            t3 += rep * inc;
        }
        float den = fmaxf(cnt, 1.f);
        if (out_size > 0) out[0] = (cnt > 0.f) ? t0 / den : 0.f;
        if (out_size > 1) out[1] = t1 / den;
        if (out_size > 2) out[2] = t2 / den;
        if (out_size > 3) out[3] = t3 / den;
    }
}

extern "C" void kernel_launch(void* const* d_in, const int* in_sizes, int n_in,
                              void* d_out, int out_size) {
    const float* beta  = (const float*)d_in[0];
    const float* embed = (const float*)d_in[1];
    const int*   sid   = (const int*)d_in[2];
    const int*   iscp  = (const int*)d_in[3];
    int N = in_sizes[0] / BB;

    dim3 ga(48, BB);
    pass_a<<<ga, TPB>>>(beta, sid, iscp, N);
    gather_ref<<<(BB*KK*4 + 511) / 512, 512>>>(embed, N);
    int NC = (N + PPC - 1) / PPC;
    dim3 gc(NC + 2, BB);
    pass_c<<<gc, TPB>>>(beta, embed, sid, N, NC);
    finalize_kernel<<<1, 512>>>((float*)d_out, out_size);
}

// round 6
// speedup vs baseline: 2.0327x; 1.6409x over previous
#include <cuda_runtime.h>
#include <math.h>
#include <limits.h>
#include <stdint.h>

#define BB 8
#define KK 512
#define DD 16
#define MAX_CPN 512
#define CPBUF 1024
#define BG_W 2.0f

#define TPB 256
#define PPC 2048
#define UC 4

// ---------------- device scratch (all-zero == clean state; finalize re-zeros) ----------------
__device__ float4 g_acc[BB*KK];        // {cnt, sumexp, dsum, pad}
__device__ int    g_cpcnt[BB*KK];
__device__ int    g_fimax[BB*KK];      // 0 = none, else (N - first_cp_index)
__device__ float  g_cpbeta[BB*KK];
__device__ float  g_ref[BB*KK*DD];
__device__ int    g_ncp[BB];
__device__ int    g_nbg[BB];
__device__ float  g_bgsig[BB];
__device__ int    g_cpidx[BB*CPBUF];
__device__ float  g_rep[BB];

__device__ __forceinline__ float dist16(float4 a0, float4 a1, float4 a2, float4 a3,
                                        float4 b0, float4 b1, float4 b2, float4 b3) {
    float d = 0.f, df;
    df = a0.x-b0.x; d += df*df; df = a0.y-b0.y; d += df*df;
    df = a0.z-b0.z; d += df*df; df = a0.w-b0.w; d += df*df;
    df = a1.x-b1.x; d += df*df; df = a1.y-b1.y; d += df*df;
    df = a1.z-b1.z; d += df*df; df = a1.w-b1.w; d += df*df;
    df = a2.x-b2.x; d += df*df; df = a2.y-b2.y; d += df*df;
    df = a2.z-b2.z; d += df*df; df = a2.w-b2.w; d += df*df;
    df = a3.x-b3.x; d += df*df; df = a3.y-b3.y; d += df*df;
    df = a3.z-b3.z; d += df*df; df = a3.w-b3.w; d += df*df;
    return d;
}

// ---------------- pass A: light-array stats (int4/float4 vectorized) ----------------
__global__ void __launch_bounds__(TPB)
pass_a(const float* __restrict__ beta, const int* __restrict__ sid,
       const int* __restrict__ iscp, int N) {
    int b = blockIdx.y;
    const int4*   s4p = (const int4*)(sid  + (size_t)b * N);
    const int4*   c4p = (const int4*)(iscp + (size_t)b * N);
    const float4* b4p = (const float4*)(beta + (size_t)b * N);
    int NG = N >> 2;
    int gt = blockIdx.x * TPB + threadIdx.x;
    int G  = gridDim.x * TPB;
    float bgs = 0.f; int bgc = 0;

    for (int j = gt; j < NG; j += G) {
        int4   s4 = s4p[j];
        int4   c4 = c4p[j];
        float4 bt = b4p[j];
        int   ss[4] = { s4.x, s4.y, s4.z, s4.w };
        int   cc[4] = { c4.x, c4.y, c4.z, c4.w };
        float bv[4] = { bt.x, bt.y, bt.z, bt.w };
        int bi = j << 2;
        #pragma unroll
        for (int e = 0; e < 4; e++) {
            int s = ss[e];
            if (s < 0) { bgc++; bgs += 1.f / (1.f + __expf(-bv[e])); }
            if (cc[e] == 1) {
                if (s >= 0) {
                    int gi = b*KK + s;
                    atomicAdd(&g_cpcnt[gi], 1);
                    atomicAdd(&g_cpbeta[gi], bv[e]);
                    atomicMax(&g_fimax[gi], N - (bi + e));
                }
                int pos = atomicAdd(&g_ncp[b], 1);
                if (pos < CPBUF) g_cpidx[b*CPBUF + pos] = bi + e;
            }
        }
    }
    for (int i = (NG << 2) + gt; i < N; i += G) {   // tail
        int s = sid[(size_t)b*N + i];
        int c = iscp[(size_t)b*N + i];
        float btv = beta[(size_t)b*N + i];
        if (s < 0) { bgc++; bgs += 1.f / (1.f + __expf(-btv)); }
        if (c == 1) {
            if (s >= 0) {
                int gi = b*KK + s;
                atomicAdd(&g_cpcnt[gi], 1);
                atomicAdd(&g_cpbeta[gi], btv);
                atomicMax(&g_fimax[gi], N - i);
            }
            int pos = atomicAdd(&g_ncp[b], 1);
            if (pos < CPBUF) g_cpidx[b*CPBUF + pos] = i;
        }
    }
    for (int o = 16; o > 0; o >>= 1) {
        bgs += __shfl_down_sync(0xffffffffu, bgs, o);
        bgc += __shfl_down_sync(0xffffffffu, bgc, o);
    }
    if ((threadIdx.x & 31) == 0 && bgc > 0) {
        atomicAdd(&g_bgsig[b], bgs);
        atomicAdd(&g_nbg[b], bgc);
    }
}

// ---------------- pass B: gather reference embeddings ----------------
__global__ void __launch_bounds__(512)
gather_ref(const float* __restrict__ embed, int N) {
    int gt = blockIdx.x * 512 + threadIdx.x;
    if (gt >= BB*KK*4) return;
    int gi = gt >> 2, comp = gt & 3;
    int b = gi >> 9;
    int fm = g_fimax[gi];
    float4 v = make_float4(0.f, 0.f, 0.f, 0.f);
    if (g_cpcnt[gi] >= 1 && fm > 0) {
        int fi = N - fm;
        v = ((const float4*)(embed + (size_t)b*N*DD + (size_t)fi*DD))[comp];
    }
    ((float4*)g_ref)[gi*4 + comp] = v;
}

// ---------------- pass C (quad-split, coalesced) + fused repulsion blocks ----------------
__global__ void __launch_bounds__(TPB)
pass_c(const float* __restrict__ beta, const float* __restrict__ embed,
       const int* __restrict__ sid, int N, int NC) {
    __shared__ float4 s_tab[KK*4];   // 32 KB
    int b = blockIdx.y;
    int t = threadIdx.x;

    if (blockIdx.x < NC) {
        // ----- main embed stream -----
        const float4* gr = (const float4*)&g_ref[(size_t)b*KK*DD];
        for (int k = t; k < KK*4; k += TPB) s_tab[k] = gr[k];
        __syncthreads();

        const float*  betB = beta  + (size_t)b * N;
        const float*  embB = embed + (size_t)b * N * DD;
        const int*    sidB = sid   + (size_t)b * N;
        const float4* ef4  = (const float4*)embB;
        float4* accB = &g_acc[b*KK];

        int base = blockIdx.x * PPC;
        int end  = min(base + PPC, N);
        int q = t >> 2;       // point-in-group 0..63
        int c = t & 3;        // component quad lane

        for (int i0 = base + q; i0 < end; i0 += 64 * UC) {
            int   s[UC]; float bt[UC]; float4 e[UC];
            #pragma unroll
            for (int u = 0; u < UC; u++) {
                int i = i0 + u * 64;
                bool act = i < end;
                s[u]  = act ? sidB[i] : -1;
                bt[u] = act ? betB[i] : 0.f;
                e[u]  = act ? ef4[(size_t)i * 4 + c] : make_float4(0.f,0.f,0.f,0.f);
            }
            #pragma unroll
            for (int u = 0; u < UC; u++) {
                int ui = max(s[u], 0);
                float4 r = s_tab[(ui << 2) | c];
                float df, pd = 0.f;
                df = e[u].x - r.x; pd += df*df;
                df = e[u].y - r.y; pd += df*df;
                df = e[u].z - r.z; pd += df*df;
                df = e[u].w - r.w; pd += df*df;
                pd += __shfl_xor_sync(0xffffffffu, pd, 1);
                pd += __shfl_xor_sync(0xffffffffu, pd, 2);
                if (c == 0 && s[u] >= 0) {
                    atomicAdd(&accB[s[u]], make_float4(1.f, __expf(bt[u]), pd, 0.f));
                }
            }
        }
    } else {
        // ----- repulsion: 2 blocks per batch, broadcast j-loop -----
        int half = blockIdx.x - NC;   // 0 or 1
        int P = g_ncp[b]; if (P > MAX_CPN) P = MAX_CPN;
        const float4* embB = (const float4*)(embed + (size_t)b * N * DD);
        for (int k = t; k < KK*4; k += TPB) {
            int jj = k >> 2;
            float4 v = make_float4(0.f, 0.f, 0.f, 0.f);
            if (jj < P) v = embB[(size_t)g_cpidx[b*CPBUF + jj] * 4 + (k & 3)];
            s_tab[k] = v;
        }
        __syncthreads();

        int i = half * 256 + t;
        float acc = 0.f;
        if (i < P) {
            float4 a0 = s_tab[i*4+0], a1 = s_tab[i*4+1], a2 = s_tab[i*4+2], a3 = s_tab[i*4+3];
            #pragma unroll 2
            for (int j = 0; j < P; j++) {
                float d = dist16(a0, a1, a2, a3,
                                 s_tab[j*4+0], s_tab[j*4+1], s_tab[j*4+2], s_tab[j*4+3]);
                if (d < 30.f) acc += __expf(-d);   // exp(-30)~9e-14 negligible
            }
        }
        for (int o = 16; o > 0; o >>= 1) acc += __shfl_down_sync(0xffffffffu, acc, o);
        __shared__ float wsum[8];
        if ((t & 31) == 0) wsum[t >> 5] = acc;
        __syncthreads();
        if (t < 8) {
            float v = wsum[t];
            for (int o = 4; o > 0; o >>= 1) v += __shfl_down_sync(0xffu, v, o);
            if (t == 0 && v != 0.f) atomicAdd(&g_rep[b], v);
        }
    }
}

// ---------------- finalize + output + scratch reset (single block, NO atomics) ----------------
__global__ void __launch_bounds__(512)
finalize_kernel(float* __restrict__ out, int out_size) {
    int t = threadIdx.x;
    int lane = t & 31, warp = t >> 5;
    __shared__ float s_rce[16], s_rat[16];
    __shared__ int   s_rvl[16];
    __shared__ float s_b[BB][3];   // per-batch: ce_sum, at_sum, valid_count

    // KK == blockDim: iteration b covers batch b, one segment per thread.
    for (int b = 0; b < BB; b++) {
        int gi = b * KK + t;
        float4 a = g_acc[gi];
        int   cpc = g_cpcnt[gi];
        float cpb = g_cpbeta[gi];
        float ce = 0.f, at = 0.f; int vl = 0;
        if (a.x > 0.f && cpc == 1) { ce = __logf(fmaxf(a.y, 1e-30f)) - cpb; vl = 1; }
        if (a.x > 0.f && cpc >= 1)   at = __fdividef(a.z, fmaxf(a.x, 1.f));
        // reset scratch for next graph replay
        g_acc[gi] = make_float4(0.f, 0.f, 0.f, 0.f);
        g_cpcnt[gi] = 0; g_cpbeta[gi] = 0.f; g_fimax[gi] = 0;

        #pragma unroll
        for (int o = 16; o > 0; o >>= 1) {
            ce += __shfl_down_sync(0xffffffffu, ce, o);
            at += __shfl_down_sync(0xffffffffu, at, o);
            vl += __shfl_down_sync(0xffffffffu, vl, o);
        }
        if (lane == 0) { s_rce[warp] = ce; s_rat[warp] = at; s_rvl[warp] = vl; }
        __syncthreads();
        if (warp == 0 && lane < 16) {
            float c2 = s_rce[lane], a2 = s_rat[lane];
            int v2 = s_rvl[lane];
            #pragma unroll
            for (int o = 8; o > 0; o >>= 1) {
                c2 += __shfl_down_sync(0xffffu, c2, o);
                a2 += __shfl_down_sync(0xffffu, a2, o);
                v2 += __shfl_down_sync(0xffffu, v2, o);
            }
            if (lane == 0) { s_b[b][0] = c2; s_b[b][1] = a2; s_b[b][2] = (float)v2; }
        }
        __syncthreads();
    }

    if (t == 0) {
        float cnt = 0.f, t0 = 0.f, t1 = 0.f, t2 = 0.f, t3 = 0.f;
        for (int b = 0; b < BB; b++) {
            float sc = s_b[b][2];
            float bl = s_b[b][0] / fmaxf(sc, 1.f);
            float nbg = (float)g_nbg[b];
            if (nbg > 0.f) bl += BG_W * (g_bgsig[b] / nbg);
            float attr = s_b[b][1];
            float ncp = (float)g_ncp[b];
            float rep = (ncp > 1.f) ? g_rep[b] / fmaxf(ncp * ncp, 1.f) : 0.f;
            float inc = (sc > 0.f) ? 1.f : 0.f;
            cnt += inc;
            t0 += (bl + attr + rep) * inc;
            t1 += bl * inc;
            t2 += attr * inc;
            t3 += rep * inc;
        }
        float den = fmaxf(cnt, 1.f);
        if (out_size > 0) out[0] = (cnt > 0.f) ? t0 / den : 0.f;
        if (out_size > 1) out[1] = t1 / den;
        if (out_size > 2) out[2] = t2 / den;
        if (out_size > 3) out[3] = t3 / den;
    }
    // reset per-batch scalars
    if (t < BB) { g_ncp[t] = 0; g_nbg[t] = 0; g_bgsig[t] = 0.f; g_rep[t] = 0.f; }
}

extern "C" void kernel_launch(void* const* d_in, const int* in_sizes, int n_in,
                              void* d_out, int out_size) {
    const float* beta  = (const float*)d_in[0];
    const float* embed = (const float*)d_in[1];
    const int*   sid   = (const int*)d_in[2];
    const int*   iscp  = (const int*)d_in[3];
    int N = in_sizes[0] / BB;

    dim3 ga(48, BB);
    pass_a<<<ga, TPB>>>(beta, sid, iscp, N);
    gather_ref<<<(BB*KK*4 + 511) / 512, 512>>>(embed, N);
    int NC = (N + PPC - 1) / PPC;
    dim3 gc(NC + 2, BB);
    pass_c<<<gc, TPB>>>(beta, embed, sid, N, NC);
    finalize_kernel<<<1, 512>>>((float*)d_out, out_size);
}

// round 7
// speedup vs baseline: 2.0764x; 1.0215x over previous
#include <cuda_runtime.h>
#include <math.h>
#include <limits.h>
#include <stdint.h>

#define BB 8
#define KK 512
#define DD 16
#define MAX_CPN 512
#define CPBUF 1024
#define BG_W 2.0f

#define TPB 256
#define PPC 2048
#define UC 4

// ---------------- device scratch (all-zero == clean state; finalize re-zeros) ----------------
__device__ int    g_cnt[BB*KK];
__device__ float  g_sumexp[BB*KK];
__device__ float  g_dsum[BB*KK];
__device__ int    g_cpcnt[BB*KK];
__device__ int    g_fimax[BB*KK];      // 0 = none, else (N - first_cp_index)
__device__ float  g_cpbeta[BB*KK];
__device__ float  g_ref[BB*KK*DD];
__device__ int    g_ncp[BB];
__device__ int    g_nbg[BB];
__device__ float  g_bgsig[BB];
__device__ int    g_cpidx[BB*CPBUF];
__device__ float  g_rep[BB];
__device__ float  g_batch[BB*5];
__device__ unsigned g_tick;

__device__ __forceinline__ float dist16(float4 a0, float4 a1, float4 a2, float4 a3,
                                        float4 b0, float4 b1, float4 b2, float4 b3) {
    float d = 0.f, df;
    df = a0.x-b0.x; d += df*df; df = a0.y-b0.y; d += df*df;
    df = a0.z-b0.z; d += df*df; df = a0.w-b0.w; d += df*df;
    df = a1.x-b1.x; d += df*df; df = a1.y-b1.y; d += df*df;
    df = a1.z-b1.z; d += df*df; df = a1.w-b1.w; d += df*df;
    df = a2.x-b2.x; d += df*df; df = a2.y-b2.y; d += df*df;
    df = a2.z-b2.z; d += df*df; df = a2.w-b2.w; d += df*df;
    df = a3.x-b3.x; d += df*df; df = a3.y-b3.y; d += df*df;
    df = a3.z-b3.z; d += df*df; df = a3.w-b3.w; d += df*df;
    return d;
}

// ---------------- pass A: light-array stats + cnt/sumexp via shared K-arrays ----------------
__global__ void __launch_bounds__(TPB)
pass_a(const float* __restrict__ beta, const int* __restrict__ sid,
       const int* __restrict__ iscp, int N) {
    __shared__ int   s_cnt[KK];
    __shared__ float s_sx[KK];
    int b = blockIdx.y;
    int t = threadIdx.x;
    for (int k = t; k < KK; k += TPB) { s_cnt[k] = 0; s_sx[k] = 0.f; }
    __syncthreads();

    const int4*   s4p = (const int4*)(sid  + (size_t)b * N);
    const int4*   c4p = (const int4*)(iscp + (size_t)b * N);
    const float4* b4p = (const float4*)(beta + (size_t)b * N);
    int NG = N >> 2;
    int gt = blockIdx.x * TPB + t;
    int G  = gridDim.x * TPB;
    float bgs = 0.f; int bgc = 0;

    for (int j = gt; j < NG; j += G) {
        int4   s4 = s4p[j];
        int4   c4 = c4p[j];
        float4 bt = b4p[j];
        int   ss[4] = { s4.x, s4.y, s4.z, s4.w };
        int   cc[4] = { c4.x, c4.y, c4.z, c4.w };
        float bv[4] = { bt.x, bt.y, bt.z, bt.w };
        int bi = j << 2;
        #pragma unroll
        for (int e = 0; e < 4; e++) {
            int s = ss[e];
            if (s < 0) {
                bgc++; bgs += 1.f / (1.f + __expf(-bv[e]));
            } else {
                atomicAdd(&s_cnt[s], 1);
                atomicAdd(&s_sx[s], __expf(bv[e]));
            }
            if (cc[e] == 1) {
                if (s >= 0) {
                    int gi = b*KK + s;
                    atomicAdd(&g_cpcnt[gi], 1);
                    atomicAdd(&g_cpbeta[gi], bv[e]);
                    atomicMax(&g_fimax[gi], N - (bi + e));
                }
                int pos = atomicAdd(&g_ncp[b], 1);
                if (pos < CPBUF) g_cpidx[b*CPBUF + pos] = bi + e;
            }
        }
    }
    for (int i = (NG << 2) + gt; i < N; i += G) {   // tail
        int s = sid[(size_t)b*N + i];
        int c = iscp[(size_t)b*N + i];
        float btv = beta[(size_t)b*N + i];
        if (s < 0) {
            bgc++; bgs += 1.f / (1.f + __expf(-btv));
        } else {
            atomicAdd(&s_cnt[s], 1);
            atomicAdd(&s_sx[s], __expf(btv));
        }
        if (c == 1) {
            if (s >= 0) {
                int gi = b*KK + s;
                atomicAdd(&g_cpcnt[gi], 1);
                atomicAdd(&g_cpbeta[gi], btv);
                atomicMax(&g_fimax[gi], N - i);
            }
            int pos = atomicAdd(&g_ncp[b], 1);
            if (pos < CPBUF) g_cpidx[b*CPBUF + pos] = i;
        }
    }
    for (int o = 16; o > 0; o >>= 1) {
        bgs += __shfl_down_sync(0xffffffffu, bgs, o);
        bgc += __shfl_down_sync(0xffffffffu, bgc, o);
    }
    if ((t & 31) == 0 && bgc > 0) {
        atomicAdd(&g_bgsig[b], bgs);
        atomicAdd(&g_nbg[b], bgc);
    }
    __syncthreads();
    for (int k = t; k < KK; k += TPB) {
        int c = s_cnt[k];
        if (c > 0) {
            atomicAdd(&g_cnt[b*KK + k], c);
            atomicAdd(&g_sumexp[b*KK + k], s_sx[k]);
        }
    }
}

// ---------------- pass B: gather reference embeddings ----------------
__global__ void __launch_bounds__(512)
gather_ref(const float* __restrict__ embed, int N) {
    int gt = blockIdx.x * 512 + threadIdx.x;
    if (gt >= BB*KK*4) return;
    int gi = gt >> 2, comp = gt & 3;
    int b = gi >> 9;
    int fm = g_fimax[gi];
    float4 v = make_float4(0.f, 0.f, 0.f, 0.f);
    if (g_cpcnt[gi] >= 1 && fm > 0) {
        int fi = N - fm;
        v = ((const float4*)(embed + (size_t)b*N*DD + (size_t)fi*DD))[comp];
    }
    ((float4*)g_ref)[gi*4 + comp] = v;
}

// ---------------- pass C (quad-split, coalesced; scalar RED) + fused repulsion ----------------
__global__ void __launch_bounds__(TPB)
pass_c(const float* __restrict__ embed, const int* __restrict__ sid, int N, int NC) {
    __shared__ float4 s_tab[KK*4];   // 32 KB
    int b = blockIdx.y;
    int t = threadIdx.x;

    if (blockIdx.x < NC) {
        // ----- main embed stream -----
        const float4* gr = (const float4*)&g_ref[(size_t)b*KK*DD];
        for (int k = t; k < KK*4; k += TPB) s_tab[k] = gr[k];
        __syncthreads();

        const float*  embB = embed + (size_t)b * N * DD;
        const int*    sidB = sid   + (size_t)b * N;
        const float4* ef4  = (const float4*)embB;
        float* dsB = &g_dsum[b*KK];

        int base = blockIdx.x * PPC;
        int end  = min(base + PPC, N);
        int q = t >> 2;       // point-in-group 0..63
        int c = t & 3;        // component quad lane

        for (int i0 = base + q; i0 < end; i0 += 64 * UC) {
            int s[UC]; float4 e[UC];
            #pragma unroll
            for (int u = 0; u < UC; u++) {
                int i = i0 + u * 64;
                bool act = i < end;
                s[u] = act ? sidB[i] : -1;
                e[u] = act ? ef4[(size_t)i * 4 + c] : make_float4(0.f,0.f,0.f,0.f);
            }
            #pragma unroll
            for (int u = 0; u < UC; u++) {
                int ui = max(s[u], 0);
                float4 r = s_tab[(ui << 2) | c];
                float df, pd = 0.f;
                df = e[u].x - r.x; pd += df*df;
                df = e[u].y - r.y; pd += df*df;
                df = e[u].z - r.z; pd += df*df;
                df = e[u].w - r.w; pd += df*df;
                pd += __shfl_xor_sync(0xffffffffu, pd, 1);
                pd += __shfl_xor_sync(0xffffffffu, pd, 2);
                if (c == 0 && s[u] >= 0) atomicAdd(&dsB[s[u]], pd);
            }
        }
    } else {
        // ----- repulsion: 2 blocks per batch, broadcast j-loop -----
        int half = blockIdx.x - NC;   // 0 or 1
        int P = g_ncp[b]; if (P > MAX_CPN) P = MAX_CPN;
        const float4* embB = (const float4*)(embed + (size_t)b * N * DD);
        for (int k = t; k < KK*4; k += TPB) {
            int jj = k >> 2;
            float4 v = make_float4(0.f, 0.f, 0.f, 0.f);
            if (jj < P) v = embB[(size_t)g_cpidx[b*CPBUF + jj] * 4 + (k & 3)];
            s_tab[k] = v;
        }
        __syncthreads();

        int i = half * 256 + t;
        float acc = 0.f;
        if (i < P) {
            float4 a0 = s_tab[i*4+0], a1 = s_tab[i*4+1], a2 = s_tab[i*4+2], a3 = s_tab[i*4+3];
            #pragma unroll 2
            for (int j = 0; j < P; j++) {
                float d = dist16(a0, a1, a2, a3,
                                 s_tab[j*4+0], s_tab[j*4+1], s_tab[j*4+2], s_tab[j*4+3]);
                if (d < 30.f) acc += __expf(-d);   // exp(-30)~9e-14 negligible
            }
        }
        for (int o = 16; o > 0; o >>= 1) acc += __shfl_down_sync(0xffffffffu, acc, o);
        __shared__ float wsum[8];
        if ((t & 31) == 0) wsum[t >> 5] = acc;
        __syncthreads();
        if (t < 8) {
            float v = wsum[t];
            for (int o = 4; o > 0; o >>= 1) v += __shfl_down_sync(0xffu, v, o);
            if (t == 0 && v != 0.f) atomicAdd(&g_rep[b], v);
        }
    }
}

// ---------------- finalize: 1 block per batch + ticket-based combine ----------------
__global__ void __launch_bounds__(512)
finalize_kernel(float* __restrict__ out, int out_size) {
    int b = blockIdx.x;
    int t = threadIdx.x;
    int lane = t & 31, warp = t >> 5;
    __shared__ float s_rce[16], s_rat[16];
    __shared__ int   s_rvl[16];
    __shared__ bool  s_last;

    int gi = b * KK + t;          // one segment per thread
    int   cnt = g_cnt[gi];
    float sx  = g_sumexp[gi];
    float ds  = g_dsum[gi];
    int   cpc = g_cpcnt[gi];
    float cpb = g_cpbeta[gi];
    float ce = 0.f, at = 0.f; int vl = 0;
    if (cnt > 0 && cpc == 1) { ce = __logf(fmaxf(sx, 1e-30f)) - cpb; vl = 1; }
    if (cnt > 0 && cpc >= 1)   at = __fdividef(ds, fmaxf((float)cnt, 1.f));

    // reset scratch slice for next graph replay
    g_cnt[gi] = 0; g_sumexp[gi] = 0.f; g_dsum[gi] = 0.f;
    g_cpcnt[gi] = 0; g_cpbeta[gi] = 0.f; g_fimax[gi] = 0;

    #pragma unroll
    for (int o = 16; o > 0; o >>= 1) {
        ce += __shfl_down_sync(0xffffffffu, ce, o);
        at += __shfl_down_sync(0xffffffffu, at, o);
        vl += __shfl_down_sync(0xffffffffu, vl, o);
    }
    if (lane == 0) { s_rce[warp] = ce; s_rat[warp] = at; s_rvl[warp] = vl; }
    __syncthreads();
    if (t == 0) {
        float c2 = 0.f, a2 = 0.f; int v2 = 0;
        #pragma unroll
        for (int w = 0; w < 16; w++) { c2 += s_rce[w]; a2 += s_rat[w]; v2 += s_rvl[w]; }
        float bl = c2 / fmaxf((float)v2, 1.f);
        float nbg = (float)g_nbg[b];
        if (nbg > 0.f) bl += BG_W * (g_bgsig[b] / nbg);
        float ncp = (float)g_ncp[b];
        float rep = (ncp > 1.f) ? g_rep[b] / fmaxf(ncp * ncp, 1.f) : 0.f;
        g_batch[b*5 + 0] = bl + a2 + rep;
        g_batch[b*5 + 1] = bl;
        g_batch[b*5 + 2] = a2;
        g_batch[b*5 + 3] = rep;
        g_batch[b*5 + 4] = (v2 > 0) ? 1.f : 0.f;
        // reset per-batch scalars
        g_ncp[b] = 0; g_nbg[b] = 0; g_bgsig[b] = 0.f; g_rep[b] = 0.f;
        __threadfence();
        unsigned tk = atomicAdd(&g_tick, 1u);
        s_last = (tk == BB - 1);
    }
    __syncthreads();
    if (s_last && t == 0) {
        __threadfence();
        float cnt2 = 0.f, t0 = 0.f, t1 = 0.f, t2 = 0.f, t3 = 0.f;
        for (int bb = 0; bb < BB; bb++) {
            float inc = g_batch[bb*5 + 4];
            cnt2 += inc;
            t0 += g_batch[bb*5 + 0] * inc;
            t1 += g_batch[bb*5 + 1] * inc;
            t2 += g_batch[bb*5 + 2] * inc;
            t3 += g_batch[bb*5 + 3] * inc;
        }
        float den = fmaxf(cnt2, 1.f);
        if (out_size > 0) out[0] = (cnt2 > 0.f) ? t0 / den : 0.f;
        if (out_size > 1) out[1] = t1 / den;
        if (out_size > 2) out[2] = t2 / den;
        if (out_size > 3) out[3] = t3 / den;
        g_tick = 0u;   // reset for next graph replay
    }
}

extern "C" void kernel_launch(void* const* d_in, const int* in_sizes, int n_in,
                              void* d_out, int out_size) {
    const float* beta  = (const float*)d_in[0];
    const float* embed = (const float*)d_in[1];
    const int*   sid   = (const int*)d_in[2];
    const int*   iscp  = (const int*)d_in[3];
    int N = in_sizes[0] / BB;

    dim3 ga(48, BB);
    pass_a<<<ga, TPB>>>(beta, sid, iscp, N);
    gather_ref<<<(BB*KK*4 + 511) / 512, 512>>>(embed, N);
    int NC = (N + PPC - 1) / PPC;
    dim3 gc(NC + 2, BB);
    pass_c<<<gc, TPB>>>(embed, sid, N, NC);
    finalize_kernel<<<BB, 512>>>((float*)d_out, out_size);
}